// round 1
// baseline (speedup 1.0000x reference)
#include <cuda_runtime.h>
#include <cstdint>

// Problem constants
#define DDIM 4096
#define NEXP 64
#define NTOK 16384          // B*S = 4*4096
#define BM   128            // rows per CTA
#define BK   32             // k per stage
#define NSTAGE (DDIM / BK)  // 128

// Output layout (tuple flattened to float32 in reference order)
#define IDX_OFF   0
#define SC_OFF    32768
#define PB_OFF    65536
#define Z_OFF     1114112
#define IMP_OFF   1114113
#define LOAD_OFF  1114177

// Global stats scratch: [0..63] importance sums, [64..127] counts, [128] z^2 sum
__device__ float g_stats[129];

// ---------- PTX helpers ----------
__device__ __forceinline__ unsigned long long ffma2(unsigned long long a,
                                                    unsigned long long b,
                                                    unsigned long long c) {
    unsigned long long d;
    asm("fma.rn.f32x2 %0, %1, %2, %3;" : "=l"(d) : "l"(a), "l"(b), "l"(c));
    return d;
}
__device__ __forceinline__ void cp8(uint32_t dst, const void* src) {
    asm volatile("cp.async.ca.shared.global [%0], [%1], 8;" :: "r"(dst), "l"(src));
}
__device__ __forceinline__ void cp16(uint32_t dst, const void* src) {
    asm volatile("cp.async.cg.shared.global [%0], [%1], 16;" :: "r"(dst), "l"(src));
}
__device__ __forceinline__ void cp_commit() {
    asm volatile("cp.async.commit_group;" ::: "memory");
}
template <int N> __device__ __forceinline__ void cp_wait() {
    asm volatile("cp.async.wait_group %0;" :: "n"(N) : "memory");
}

// ---------- init / finalize ----------
extern "C" __global__ void zero_stats_kernel() {
    int t = threadIdx.x;
    if (t < 129) g_stats[t] = 0.0f;
}

extern "C" __global__ void finalize_kernel(float* __restrict__ out) {
    int t = threadIdx.x;
    if (t < 64) {
        out[IMP_OFF + t]  = g_stats[t]      * (1.0f / 16384.0f);
        out[LOAD_OFF + t] = g_stats[64 + t] * (1.0f / 32768.0f);
    }
    if (t == 128) out[Z_OFF] = g_stats[128] * (1.0f / 16384.0f);
}

// ---------- fused GEMM + router ----------
// grid = 128 CTAs (one per 128-token tile), block = 128 threads.
// Each CTA computes logits[128][64] fully in registers/smem, then routes.
extern "C" __global__ void __launch_bounds__(128, 2)
router_kernel(const float* __restrict__ x, const float* __restrict__ W,
              float* __restrict__ out) {
    // Static smem: 12288 floats = 48KB
    //   xs0 [0..4095], ws0 [4096..6143], xs1 [6144..10239], ws1 [10240..12287]
    // Logits region (8192 floats) reuses sm[0..8191] after the mainloop.
    __shared__ float sm[12288];
    float* xs[2] = { sm,        sm + 6144 };
    float* ws[2] = { sm + 4096, sm + 10240 };
    uint32_t xs_a[2], ws_a[2];
    xs_a[0] = (uint32_t)__cvta_generic_to_shared(xs[0]);
    xs_a[1] = (uint32_t)__cvta_generic_to_shared(xs[1]);
    ws_a[0] = (uint32_t)__cvta_generic_to_shared(ws[0]);
    ws_a[1] = (uint32_t)__cvta_generic_to_shared(ws[1]);

    const int tid = threadIdx.x;
    const int tm = tid & 15;      // 0..15 -> row group
    const int tn = tid >> 4;      // 0..7  -> expert group
    const int rowbase = blockIdx.x * BM;

    // ---- stage loader (cp.async) ----
    // x tile [128 rows][32 k] with XOR pair-swizzle: pair column kc stored at kc^(row&15)
    // w tile [64 rows][32 k], plain (frag reads are broadcast-heavy, 2-way conflict OK)
    auto load_stage = [&](int s, int b) {
        const float* xg = x + (size_t)rowbase * DDIM + s * BK;
        #pragma unroll
        for (int i = 0; i < 16; i++) {
            int c = tid + 128 * i;          // 0..2047 : 128 rows x 16 pairs
            int r = c >> 4;
            int kc = c & 15;                // 8B pair index
            uint32_t dst = xs_a[b] + (uint32_t)((r * 32 + ((kc ^ (r & 15)) << 1)) * 4);
            cp8(dst, xg + (size_t)r * DDIM + (kc << 1));
        }
        const float* wg = W + s * BK;
        #pragma unroll
        for (int i = 0; i < 4; i++) {
            int c = tid + 128 * i;          // 0..511 : 64 rows x 8 quads
            int r = c >> 3;
            int q = c & 7;                  // 16B chunk index
            uint32_t dst = ws_a[b] + (uint32_t)((r * 32 + q * 4) * 4);
            cp16(dst, wg + (size_t)r * DDIM + q * 4);
        }
        cp_commit();
    };

    // f32x2 accumulators: acc[i][j] accumulates (even-k, odd-k) partial dots
    unsigned long long acc[8][8];
    #pragma unroll
    for (int i = 0; i < 8; i++)
        #pragma unroll
        for (int j = 0; j < 8; j++) acc[i][j] = 0ull;

    load_stage(0, 0);

    #pragma unroll 1
    for (int s = 0; s < NSTAGE; s++) {
        if (s + 1 < NSTAGE) {
            load_stage(s + 1, (s + 1) & 1);
            cp_wait<1>();
        } else {
            cp_wait<0>();
        }
        __syncthreads();

        const float* X  = xs[s & 1];
        const float* Wm = ws[s & 1];

        #pragma unroll 4
        for (int kp = 0; kp < 16; kp++) {       // 16 k-pairs per stage
            const int kpx = ((kp ^ tm) << 1);   // de-swizzle (row&15 == tm for all our rows)
            unsigned long long xv[8], wv[8];
            #pragma unroll
            for (int i = 0; i < 8; i++)
                xv[i] = *(const unsigned long long*)(X + (tm + 16 * i) * 32 + kpx);
            #pragma unroll
            for (int j = 0; j < 8; j++)
                wv[j] = *(const unsigned long long*)(Wm + (tn + 8 * j) * 32 + (kp << 1));
            #pragma unroll
            for (int i = 0; i < 8; i++)
                #pragma unroll
                for (int j = 0; j < 8; j++)
                    acc[i][j] = ffma2(xv[i], wv[j], acc[i][j]);
        }
        __syncthreads();
    }

    // ---- epilogue: logits -> smem (reuse buffers; all reads fenced by last sync) ----
    float* ls = sm;  // [128][64]
    #pragma unroll
    for (int i = 0; i < 8; i++)
        #pragma unroll
        for (int j = 0; j < 8; j++) {
            float lo = __uint_as_float((uint32_t)(acc[i][j] & 0xffffffffull));
            float hi = __uint_as_float((uint32_t)(acc[i][j] >> 32));
            ls[(tm + 16 * i) * 64 + (tn + 8 * j)] = lo + hi;
        }
    __syncthreads();

    // ---- router: one warp per row, 32 rows per warp ----
    const int warp = tid >> 5;
    const int lane = tid & 31;
    const float NEG_INF = __int_as_float(0xff800000u);
    float imp0 = 0.f, imp1 = 0.f, cnt0 = 0.f, cnt1 = 0.f, z2 = 0.f;
    float* probs_out = out + PB_OFF;

    #pragma unroll 1
    for (int it = 0; it < 32; it++) {
        const int rl = warp * 32 + it;
        const int row = rowbase + rl;
        const float va = ls[rl * 64 + lane];
        const float vb = ls[rl * 64 + lane + 32];

        // top-1 (ties -> lower index, matching lax.top_k)
        float bv; int bi;
        if (va >= vb) { bv = va; bi = lane; } else { bv = vb; bi = lane + 32; }
        #pragma unroll
        for (int off = 16; off; off >>= 1) {
            float ov = __shfl_xor_sync(0xffffffffu, bv, off);
            int   oi = __shfl_xor_sync(0xffffffffu, bi, off);
            if (ov > bv || (ov == bv && oi < bi)) { bv = ov; bi = oi; }
        }
        // top-2 (exclude bi)
        float va2 = (lane == bi)      ? NEG_INF : va;
        float vb2 = (lane + 32 == bi) ? NEG_INF : vb;
        float sv; int si;
        if (va2 >= vb2) { sv = va2; si = lane; } else { sv = vb2; si = lane + 32; }
        #pragma unroll
        for (int off = 16; off; off >>= 1) {
            float ov = __shfl_xor_sync(0xffffffffu, sv, off);
            int   oi = __shfl_xor_sync(0xffffffffu, si, off);
            if (ov > sv || (ov == sv && oi < si)) { sv = ov; si = oi; }
        }

        // full softmax (max-shifted)
        const float ea = expf(va - bv);
        const float eb = expf(vb - bv);
        float ssum = ea + eb;
        #pragma unroll
        for (int off = 16; off; off >>= 1)
            ssum += __shfl_xor_sync(0xffffffffu, ssum, off);
        const float inv = 1.0f / ssum;
        const float pa = ea * inv, pb = eb * inv;

        probs_out[(size_t)row * 64 + lane]      = pa;
        probs_out[(size_t)row * 64 + lane + 32] = pb;

        imp0 += pa; imp1 += pb;
        cnt0 += (bi == lane      ? 1.f : 0.f) + (si == lane      ? 1.f : 0.f);
        cnt1 += (bi == lane + 32 ? 1.f : 0.f) + (si == lane + 32 ? 1.f : 0.f);

        if (lane == 0) {
            const float z = bv + logf(ssum);       // logsumexp
            z2 += z * z;
            out[IDX_OFF + row * 2]     = (float)bi;
            out[IDX_OFF + row * 2 + 1] = (float)si;
            const float e2 = expf(sv - bv);        // renormalized top-2 softmax
            const float dn = 1.0f / (1.0f + e2);
            out[SC_OFF + row * 2]     = dn;
            out[SC_OFF + row * 2 + 1] = e2 * dn;
        }
    }

    atomicAdd(&g_stats[lane],       imp0);
    atomicAdd(&g_stats[lane + 32],  imp1);
    atomicAdd(&g_stats[64 + lane],  cnt0);
    atomicAdd(&g_stats[96 + lane],  cnt1);
    if (lane == 0) atomicAdd(&g_stats[128], z2);
}

extern "C" void kernel_launch(void* const* d_in, const int* in_sizes, int n_in,
                              void* d_out, int out_size) {
    const float* x = (const float*)d_in[0];       // [4,4096,4096] f32
    const float* W = (const float*)d_in[1];       // [64,4096] f32
    float* out = (float*)d_out;
    (void)in_sizes; (void)n_in; (void)out_size;

    zero_stats_kernel<<<1, 129>>>();
    router_kernel<<<NTOK / BM, 128>>>(x, W, out);
    finalize_kernel<<<1, 129>>>(out);
}